// round 15
// baseline (speedup 1.0000x reference)
#include <cuda_runtime.h>

// CellListComputer: cell-list build, 100k atoms, 20^3 buckets, sm_103a.
// Output layout (float32): [pairs_u | pairs_l | lower_between | frac | imidx | atidx]
// 4 launches:
//   k_bucket : bucketize + per-bucket atomic counts; last block: u64 scan -> cum,poff,P
//   k_seg    : warp/bucket: MERGED segment table (typ. <=4 segs) -> g_segtab
//   k_place  : placement via atomicAdd; copies bucket segtab to per-atom g_atab
//              (packs T|nseg<<16 and aoffL); scan -> L,F,bpre
//   k_emit   : [warp/atom: compute-direct fill, 1-deep prologue load]
//              [bucket warps: sort + pairs + state cleanup] [frac]
// State invariant: g_counts/g_fill/g_done* zero on entry (static zero-init first
// call; k_emit bucket warps restore zeros every call).

#define MAXN   100000
#define MAXB   8192
#define MAXCH  104
#define ATCAP  64

__device__ int g_grid[3];
__device__ int g_scal[3];
__device__ int g_B;
__device__ int g_P;
__device__ int g_L;
__device__ int g_F;          // 2*P + L (start of frac section)
__device__ unsigned g_done1, g_done2;

__device__ __align__(16) int g_counts[MAXB];
__device__ __align__(16) int g_fill[MAXB];
__device__ __align__(16) int g_cum[MAXB];
__device__ __align__(16) int g_poff[MAXB];
// [bkt][j<7] = {start_k, f32(cum-start)}; unused -> {INT_MAX,0}; [bkt][7] = {T, nseg}
__device__ __align__(16) int2 g_segtab[MAXB * 8];
// per-atom copy: [i][j<7] = segments; [i][7] = {T | nseg<<16, aoffL}
__device__ __align__(16) int2 g_atab[MAXN * 8];
__device__ int g_vec[MAXN];                  // packed vx | vy<<8 | vz<<16
__device__ int g_tmp[MAXN];                  // unordered bucket-sliced atom indices
__device__ int g_bsum[MAXCH];
__device__ int g_bpre[MAXCH];

// inclusive block scan (int), blockDim.x == 1024
__device__ __forceinline__ int blkscan1024(int v, int* wsum) {
    int t = threadIdx.x, lane = t & 31, w = t >> 5;
    #pragma unroll
    for (int o = 1; o < 32; o <<= 1) {
        int x = __shfl_up_sync(0xffffffffu, v, o);
        if (lane >= o) v += x;
    }
    if (lane == 31) wsum[w] = v;
    __syncthreads();
    if (w == 0) {
        int s = wsum[lane];
        #pragma unroll
        for (int o = 1; o < 32; o <<= 1) {
            int x = __shfl_up_sync(0xffffffffu, s, o);
            if (lane >= o) s += x;
        }
        wsum[lane] = s;
    }
    __syncthreads();
    return v + ((w > 0) ? wsum[w - 1] : 0);
}

// inclusive block scan (u64 packed), blockDim.x == 1024
__device__ __forceinline__ unsigned long long
blkscan1024_u64(unsigned long long v, unsigned long long* wsum) {
    int t = threadIdx.x, lane = t & 31, w = t >> 5;
    #pragma unroll
    for (int o = 1; o < 32; o <<= 1) {
        unsigned long long x = __shfl_up_sync(0xffffffffu, v, o);
        if (lane >= o) v += x;
    }
    if (lane == 31) wsum[w] = v;
    __syncthreads();
    if (w == 0) {
        unsigned long long s = wsum[lane];
        #pragma unroll
        for (int o = 1; o < 32; o <<= 1) {
            unsigned long long x = __shfl_up_sync(0xffffffffu, s, o);
            if (lane >= o) s += x;
        }
        wsum[lane] = s;
    }
    __syncthreads();
    return v + ((w > 0) ? wsum[w - 1] : 0ull);
}

// bucketize + count; last-arriving block scans buckets -> g_cum, g_poff, g_P
__global__ void k_bucket(const float* __restrict__ coord,
                         const float* __restrict__ cell, int n) {
    int i = blockIdx.x * 1024 + threadIdx.x;
    float d0 = __ldg(cell + 0), d1 = __ldg(cell + 4), d2 = __ldg(cell + 8);
    float bl = (float)(5.2 / 1.0 + 1e-5);
    int g0 = (int)floorf(d0 / bl) + 1;
    int g1 = (int)floorf(d1 / bl) + 1;
    int g2 = (int)floorf(d2 / bl) + 1;
    if (blockIdx.x == 0 && threadIdx.x == 0) {
        g_grid[0] = g0; g_grid[1] = g1; g_grid[2] = g2;
        g_B = g0 * g1 * g2;
        g_scal[0] = g1 * g2; g_scal[1] = g1; g_scal[2] = 1;
    }
    if (i < n) {
        float fx = __ldg(coord + 3 * i + 0) / d0;
        float fy = __ldg(coord + 3 * i + 1) / d1;
        float fz = __ldg(coord + 3 * i + 2) / d2;
        int vx = __float2int_rn(fx * (float)(g0 - 1));
        int vy = __float2int_rn(fy * (float)(g1 - 1));
        int vz = __float2int_rn(fz * (float)(g2 - 1));
        int flat = vx * (g1 * g2) + vy * g1 + vz;   // scal = [g1*g2, g1, 1]
        g_vec[i] = vx | (vy << 8) | (vz << 16);
        atomicAdd(&g_counts[flat], 1);
    }
    __syncthreads();
    __shared__ int lastflag;
    if (threadIdx.x == 0) {
        __threadfence();
        lastflag = (atomicAdd(&g_done1, 1) == gridDim.x - 1);
    }
    __syncthreads();
    if (!lastflag) return;

    // ---- bucket scan: counts + pair-counts packed in u64, 8 buckets/thread ----
    __shared__ unsigned long long ws64[32];
    int t = threadIdx.x;
    int cc[8], eC[8], eP[8];
    #pragma unroll
    for (int j = 0; j < 8; ++j) cc[j] = __ldcg(&g_counts[t * 8 + j]);
    int sC = 0, sP = 0;
    #pragma unroll
    for (int j = 0; j < 8; ++j) {
        eC[j] = sC; sC += cc[j];
        eP[j] = sP; sP += cc[j] * (cc[j] - 1) / 2;
    }
    unsigned long long v = ((unsigned long long)(unsigned)sC << 32) | (unsigned)sP;
    unsigned long long incl = blkscan1024_u64(v, ws64);
    unsigned long long excl = incl - v;
    int baseC = (int)(excl >> 32);
    int baseP = (int)(excl & 0xffffffffull);
    int4 oc0 = make_int4(baseC + eC[0], baseC + eC[1], baseC + eC[2], baseC + eC[3]);
    int4 oc1 = make_int4(baseC + eC[4], baseC + eC[5], baseC + eC[6], baseC + eC[7]);
    int4 op0 = make_int4(baseP + eP[0], baseP + eP[1], baseP + eP[2], baseP + eP[3]);
    int4 op1 = make_int4(baseP + eP[4], baseP + eP[5], baseP + eP[6], baseP + eP[7]);
    *reinterpret_cast<int4*>(&g_cum[t * 8])      = oc0;
    *reinterpret_cast<int4*>(&g_cum[t * 8 + 4])  = oc1;
    *reinterpret_cast<int4*>(&g_poff[t * 8])     = op0;
    *reinterpret_cast<int4*>(&g_poff[t * 8 + 4]) = op1;
    if (t == 1023) g_P = (int)(incl & 0xffffffffull);
}

// warp per bucket: merged segment table -> g_segtab
__global__ void k_seg() {
    const unsigned FULL = 0xffffffffu;
    int t = threadIdx.x, wib = t >> 5, lane = t & 31;
    int bkt = blockIdx.x * 32 + wib;
    if (bkt >= g_B) return;

    int cnt = 0, cum = 0;
    if (lane < 7) {
        int s0 = g_scal[0], s1g = g_scal[1];
        int g0 = g_grid[0], g1 = g_grid[1], g2 = g_grid[2];
        int vx = bkt / s0; int r = bkt - vx * s0;
        int vy = r / s1g;  int vz = r - vy * s1g;
        int dx = (lane >> 2) - 1;
        int dy = ((lane >> 1) & 1) - 1;
        int dz = (lane & 1) - 1;
        int nx = vx + dx; if (nx < 0) nx += g0;
        int ny = vy + dy; if (ny < 0) ny += g1;
        int nz = vz + dz; if (nz < 0) nz += g2;
        int nb = nx * s0 + ny * s1g + nz;
        cnt = __ldg(&g_counts[nb]);
        cum = __ldg(&g_cum[nb]);
    }
    int nseg = 0, kpos = 0, curST = 0, curCUM = 0;
    long long b8 = (long long)bkt * 8;
    #pragma unroll
    for (int d = 0; d < 7; ++d) {
        int cd = __shfl_sync(FULL, cnt, d);
        int md = __shfl_sync(FULL, cum, d);
        if (lane == 0 && cd > 0) {
            bool ext = (nseg > 0) && (md == curCUM + (kpos - curST));
            if (!ext) {
                curST = kpos; curCUM = md;
                g_segtab[b8 + nseg] = make_int2(kpos, __float_as_int((float)(md - kpos)));
                ++nseg;
            }
            kpos += cd;
        }
    }
    if (lane == 0) {
        for (int j = nseg; j < 7; ++j)
            g_segtab[b8 + j] = make_int2(0x7FFFFFFF, 0);
        g_segtab[b8 + 7] = make_int2(kpos, nseg);
    }
}

// placement + per-atom inline segment table; last block: L, F, bpre
__global__ void k_place(int n, int nch) {
    __shared__ int ws[32];
    int t = threadIdx.x;
    int i = blockIdx.x * 1024 + t;
    bool valid = (i < n);
    int tsum = 0;
    int4 a0, a1, a2, a3;
    if (valid) {
        int pk = g_vec[i];
        int vx = pk & 0xFF, vy = (pk >> 8) & 0xFF, vz = (pk >> 16) & 0xFF;
        int flat = vx * g_scal[0] + vy * g_scal[1] + vz;
        int slot = g_cum[flat] + atomicAdd(&g_fill[flat], 1);
        g_tmp[slot] = i;
        const int4* st = reinterpret_cast<const int4*>(&g_segtab[flat * 8]);
        a0 = __ldg(st + 0);
        a1 = __ldg(st + 1);
        a2 = __ldg(st + 2);
        a3 = __ldg(st + 3);           // {seg6.x, seg6.y, T, nseg}
        tsum = a3.z;
    }
    int incl = blkscan1024(tsum, ws);
    if (valid) {
        int4* at = reinterpret_cast<int4*>(&g_atab[(long long)i * 8]);
        int nseg = a3.w;
        a3.z = tsum | (nseg << 16);   // pack T | nseg<<16
        a3.w = incl - tsum;           // aoffL
        at[0] = a0; at[1] = a1; at[2] = a2; at[3] = a3;
    }
    if (t == 1023) g_bsum[blockIdx.x] = incl;

    __syncthreads();
    __shared__ int lastflag;
    if (t == 0) {
        __threadfence();
        lastflag = (atomicAdd(&g_done2, 1) == nch - 1);
    }
    __syncthreads();
    if (!lastflag) return;

    if (t < 32) {
        const unsigned FULL = 0xffffffffu;
        int ex[4];
        int s = 0;
        #pragma unroll
        for (int j = 0; j < 4; ++j) {
            int idx = t * 4 + j;
            int x = (idx < nch) ? __ldcg(&g_bsum[idx]) : 0;
            ex[j] = s; s += x;
        }
        int iw = s;
        #pragma unroll
        for (int o = 1; o < 32; o <<= 1) {
            int x = __shfl_up_sync(FULL, iw, o);
            if (t >= o) iw += x;
        }
        int base = iw - s;
        #pragma unroll
        for (int j = 0; j < 4; ++j) {
            int idx = t * 4 + j;
            if (idx < nch) g_bpre[idx] = base + ex[j];
        }
        if (t == 31) { g_L = iw; g_F = 2 * g_P + iw; }
    }
}

// Fused output writer + state cleanup.
__global__ void k_emit(float* __restrict__ out,
                       const float* __restrict__ coord,
                       const float* __restrict__ cell,
                       int n, int fillb, int bktb) {
    const unsigned FULL = 0xffffffffu;
    int blk = blockIdx.x;
    int t = threadIdx.x;
    if (blk < fillb) {
        // ---- lower_between: warp per atom; single 64B prologue load ----
        int wib = t >> 5, lane = t & 31;
        int w = blk * 32 + wib;
        if (w >= n) return;
        int2 e = make_int2(0x7FFFFFFF, 0);
        if (lane < 8) e = __ldg(&g_atab[(long long)w * 8 + lane]);
        int TN   = __shfl_sync(FULL, e.x, 7);       // T | nseg<<16
        int aoff = __shfl_sync(FULL, e.y, 7);       // aoffL
        int T    = TN & 0xFFFF;
        int nseg = TN >> 16;
        int base = 2 * g_P + aoff + __ldg(&g_bpre[w >> 10]);
        float f0 = __shfl_sync(FULL, __int_as_float(e.y), 0);
        int   s1 = __shfl_sync(FULL, e.x, 1); float f1 = __shfl_sync(FULL, __int_as_float(e.y), 1);
        int   s2 = __shfl_sync(FULL, e.x, 2); float f2 = __shfl_sync(FULL, __int_as_float(e.y), 2);
        int   s3 = __shfl_sync(FULL, e.x, 3); float f3 = __shfl_sync(FULL, __int_as_float(e.y), 3);
        float* p = out + base + lane;
        float kf = (float)lane;
        if (nseg <= 4) {
            for (int k = lane; k < T; k += 32, kf += 32.0f, p += 32) {
                float s = f0;
                if (k >= s1) s = f1;
                if (k >= s2) s = f2;
                if (k >= s3) s = f3;
                *p = s + kf;
            }
        } else {
            int   s4 = __shfl_sync(FULL, e.x, 4); float f4 = __shfl_sync(FULL, __int_as_float(e.y), 4);
            int   s5 = __shfl_sync(FULL, e.x, 5); float f5 = __shfl_sync(FULL, __int_as_float(e.y), 5);
            int   s6 = __shfl_sync(FULL, e.x, 6); float f6 = __shfl_sync(FULL, __int_as_float(e.y), 6);
            for (int k = lane; k < T; k += 32, kf += 32.0f, p += 32) {
                float s = f0;
                if (k >= s1) s = f1;
                if (k >= s2) s = f2;
                if (k >= s3) s = f3;
                if (k >= s4) s = f4;
                if (k >= s5) s = f5;
                if (k >= s6) s = f6;
                *p = s + kf;
            }
        }
    } else if (blk < fillb + bktb) {
        // ---- warp per bucket: stable order restore + pairs + cleanup ----
        __shared__ int s_atom[32][ATCAP];
        int wib = t >> 5, lane = t & 31;
        int bkt = (blk - fillb) * 32 + wib;
        if (bkt >= g_B) return;
        if (blk == fillb && t == 0) { g_done1 = 0; g_done2 = 0; }
        int c = g_counts[bkt];
        if (lane == 0) { g_counts[bkt] = 0; g_fill[bkt] = 0; }
        if (c == 0) return;
        int cum = g_cum[bkt];
        long long F = g_F;
        long long imb = F + 3LL * n;
        long long atb = F + 4LL * n;
        int cl = (c < ATCAP) ? c : ATCAP;
        for (int j = lane; j < cl; j += 32)
            s_atom[wib][j] = g_tmp[cum + j];
        __syncwarp();
        for (int j = lane; j < c; j += 32) {
            int vj = (j < ATCAP) ? s_atom[wib][j] : __ldg(&g_tmp[cum + j]);
            int rank = 0;
            for (int k = 0; k < c; ++k) {
                int vk = (k < ATCAP) ? s_atom[wib][k] : __ldg(&g_tmp[cum + k]);
                rank += (vk < vj);
            }
            int slot = cum + rank;
            out[imb + slot] = (float)vj;
            out[atb + vj]   = (float)slot;
        }
        if (c < 2) return;
        int npr = c * (c - 1) / 2;
        int off = g_poff[bkt];
        int P = g_P;
        float cumf = (float)cum;
        for (int k = lane; k < npr; k += 32) {
            int pl = (int)((1.0f + sqrtf(8.0f * (float)k + 1.0f)) * 0.5f);
            while (pl * (pl - 1) / 2 > k) --pl;
            while ((pl + 1) * pl / 2 <= k) ++pl;
            int pu = k - pl * (pl - 1) / 2;
            out[off + k]     = cumf + (float)pu;
            out[P + off + k] = cumf + (float)pl;
        }
    } else {
        // ---- frac ----
        int i = (blk - fillb - bktb) * 1024 + t;
        if (i >= n) return;
        long long F = g_F;
        float d0 = __ldg(cell + 0), d1 = __ldg(cell + 4), d2 = __ldg(cell + 8);
        out[F + 3LL * i + 0] = __ldg(coord + 3 * i + 0) / d0;
        out[F + 3LL * i + 1] = __ldg(coord + 3 * i + 1) / d1;
        out[F + 3LL * i + 2] = __ldg(coord + 3 * i + 2) / d2;
    }
}

extern "C" void kernel_launch(void* const* d_in, const int* in_sizes, int n_in,
                              void* d_out, int out_size) {
    const float* coord = (const float*)d_in[0];
    const float* cell  = (const float*)d_in[1];
    float* out = (float*)d_out;
    int n = in_sizes[0] / 3;
    int nblk = (n + 1023) / 1024;       // 98

    k_bucket<<<nblk, 1024>>>(coord, cell, n);
    k_seg<<<MAXB / 32, 1024>>>();
    k_place<<<nblk, 1024>>>(n, nblk);

    int fillb = (n + 31) / 32;          // 3125 blocks, warp per atom
    int bktb  = MAXB / 32;              // 256 blocks, warp per bucket
    int tailb = nblk;                   // 98 blocks, frac
    k_emit<<<fillb + bktb + tailb, 1024>>>(out, coord, cell, n, fillb, bktb);
}

// round 16
// speedup vs baseline: 1.1097x; 1.1097x over previous
#include <cuda_runtime.h>

// CellListComputer: cell-list build, 100k atoms, 20^3 buckets, sm_103a.
// Output layout (float32): [pairs_u | pairs_l | lower_between | frac | imidx | atidx]
// 4 launches:
//   k_bucket : bucketize + per-bucket atomic counts; last block: u64 scan -> cum,poff,P
//   k_seg    : warp/bucket: MERGED segment table (typ. <=4 segs) -> g_segtab
//   k_place  : placement via atomicAdd; info {flat,T,aoffL}; scan -> L,F,bpre
//   k_emit   : [bucket warps FIRST: sort + pairs + cleanup (slowest blocks start in
//               wave 0, overlapped by fill)] [warp/atom fill] [frac]
// State invariant: g_counts/g_fill/g_done* zero on entry (static zero-init first
// call; k_emit bucket warps restore zeros every call; fill reads only g_segtab).

#define MAXN   100000
#define MAXB   8192
#define MAXCH  104
#define ATCAP  64

__device__ int g_grid[3];
__device__ int g_scal[3];
__device__ int g_B;
__device__ int g_P;
__device__ int g_L;
__device__ int g_F;          // 2*P + L (start of frac section)
__device__ unsigned g_done1, g_done2;

__device__ __align__(16) int g_counts[MAXB];
__device__ __align__(16) int g_fill[MAXB];
__device__ __align__(16) int g_cum[MAXB];
__device__ __align__(16) int g_poff[MAXB];
// [bkt][j<7] = {start_k, f32(cum-start)}; unused -> {INT_MAX,0}; [bkt][7] = {T, nseg}
__device__ __align__(16) int2 g_segtab[MAXB * 8];
__device__ int g_vec[MAXN];                  // packed vx | vy<<8 | vz<<16
__device__ int g_tmp[MAXN];                  // unordered bucket-sliced atom indices
__device__ __align__(16) int4 g_info[MAXN];  // per-atom {flat, T, aoffL, 0}
__device__ int g_bsum[MAXCH];
__device__ int g_bpre[MAXCH];

// inclusive block scan (int), blockDim.x == 1024
__device__ __forceinline__ int blkscan1024(int v, int* wsum) {
    int t = threadIdx.x, lane = t & 31, w = t >> 5;
    #pragma unroll
    for (int o = 1; o < 32; o <<= 1) {
        int x = __shfl_up_sync(0xffffffffu, v, o);
        if (lane >= o) v += x;
    }
    if (lane == 31) wsum[w] = v;
    __syncthreads();
    if (w == 0) {
        int s = wsum[lane];
        #pragma unroll
        for (int o = 1; o < 32; o <<= 1) {
            int x = __shfl_up_sync(0xffffffffu, s, o);
            if (lane >= o) s += x;
        }
        wsum[lane] = s;
    }
    __syncthreads();
    return v + ((w > 0) ? wsum[w - 1] : 0);
}

// inclusive block scan (u64 packed), blockDim.x == 1024
__device__ __forceinline__ unsigned long long
blkscan1024_u64(unsigned long long v, unsigned long long* wsum) {
    int t = threadIdx.x, lane = t & 31, w = t >> 5;
    #pragma unroll
    for (int o = 1; o < 32; o <<= 1) {
        unsigned long long x = __shfl_up_sync(0xffffffffu, v, o);
        if (lane >= o) v += x;
    }
    if (lane == 31) wsum[w] = v;
    __syncthreads();
    if (w == 0) {
        unsigned long long s = wsum[lane];
        #pragma unroll
        for (int o = 1; o < 32; o <<= 1) {
            unsigned long long x = __shfl_up_sync(0xffffffffu, s, o);
            if (lane >= o) s += x;
        }
        wsum[lane] = s;
    }
    __syncthreads();
    return v + ((w > 0) ? wsum[w - 1] : 0ull);
}

// bucketize + count; last-arriving block scans buckets -> g_cum, g_poff, g_P
__global__ void k_bucket(const float* __restrict__ coord,
                         const float* __restrict__ cell, int n) {
    int i = blockIdx.x * 1024 + threadIdx.x;
    float d0 = __ldg(cell + 0), d1 = __ldg(cell + 4), d2 = __ldg(cell + 8);
    float bl = (float)(5.2 / 1.0 + 1e-5);
    int g0 = (int)floorf(d0 / bl) + 1;
    int g1 = (int)floorf(d1 / bl) + 1;
    int g2 = (int)floorf(d2 / bl) + 1;
    if (blockIdx.x == 0 && threadIdx.x == 0) {
        g_grid[0] = g0; g_grid[1] = g1; g_grid[2] = g2;
        g_B = g0 * g1 * g2;
        g_scal[0] = g1 * g2; g_scal[1] = g1; g_scal[2] = 1;
    }
    if (i < n) {
        float fx = __ldg(coord + 3 * i + 0) / d0;
        float fy = __ldg(coord + 3 * i + 1) / d1;
        float fz = __ldg(coord + 3 * i + 2) / d2;
        int vx = __float2int_rn(fx * (float)(g0 - 1));
        int vy = __float2int_rn(fy * (float)(g1 - 1));
        int vz = __float2int_rn(fz * (float)(g2 - 1));
        int flat = vx * (g1 * g2) + vy * g1 + vz;   // scal = [g1*g2, g1, 1]
        g_vec[i] = vx | (vy << 8) | (vz << 16);
        atomicAdd(&g_counts[flat], 1);
    }
    __syncthreads();
    __shared__ int lastflag;
    if (threadIdx.x == 0) {
        __threadfence();
        lastflag = (atomicAdd(&g_done1, 1) == gridDim.x - 1);
    }
    __syncthreads();
    if (!lastflag) return;

    // ---- bucket scan: counts + pair-counts packed in u64, 8 buckets/thread ----
    __shared__ unsigned long long ws64[32];
    int t = threadIdx.x;
    int cc[8], eC[8], eP[8];
    #pragma unroll
    for (int j = 0; j < 8; ++j) cc[j] = __ldcg(&g_counts[t * 8 + j]);
    int sC = 0, sP = 0;
    #pragma unroll
    for (int j = 0; j < 8; ++j) {
        eC[j] = sC; sC += cc[j];
        eP[j] = sP; sP += cc[j] * (cc[j] - 1) / 2;
    }
    unsigned long long v = ((unsigned long long)(unsigned)sC << 32) | (unsigned)sP;
    unsigned long long incl = blkscan1024_u64(v, ws64);
    unsigned long long excl = incl - v;
    int baseC = (int)(excl >> 32);
    int baseP = (int)(excl & 0xffffffffull);
    int4 oc0 = make_int4(baseC + eC[0], baseC + eC[1], baseC + eC[2], baseC + eC[3]);
    int4 oc1 = make_int4(baseC + eC[4], baseC + eC[5], baseC + eC[6], baseC + eC[7]);
    int4 op0 = make_int4(baseP + eP[0], baseP + eP[1], baseP + eP[2], baseP + eP[3]);
    int4 op1 = make_int4(baseP + eP[4], baseP + eP[5], baseP + eP[6], baseP + eP[7]);
    *reinterpret_cast<int4*>(&g_cum[t * 8])      = oc0;
    *reinterpret_cast<int4*>(&g_cum[t * 8 + 4])  = oc1;
    *reinterpret_cast<int4*>(&g_poff[t * 8])     = op0;
    *reinterpret_cast<int4*>(&g_poff[t * 8 + 4]) = op1;
    if (t == 1023) g_P = (int)(incl & 0xffffffffull);
}

// warp per bucket: merged segment table -> g_segtab
__global__ void k_seg() {
    const unsigned FULL = 0xffffffffu;
    int t = threadIdx.x, wib = t >> 5, lane = t & 31;
    int bkt = blockIdx.x * 32 + wib;
    if (bkt >= g_B) return;

    int cnt = 0, cum = 0;
    if (lane < 7) {
        int s0 = g_scal[0], s1g = g_scal[1];
        int g0 = g_grid[0], g1 = g_grid[1], g2 = g_grid[2];
        int vx = bkt / s0; int r = bkt - vx * s0;
        int vy = r / s1g;  int vz = r - vy * s1g;
        int dx = (lane >> 2) - 1;
        int dy = ((lane >> 1) & 1) - 1;
        int dz = (lane & 1) - 1;
        int nx = vx + dx; if (nx < 0) nx += g0;
        int ny = vy + dy; if (ny < 0) ny += g1;
        int nz = vz + dz; if (nz < 0) nz += g2;
        int nb = nx * s0 + ny * s1g + nz;
        cnt = __ldg(&g_counts[nb]);
        cum = __ldg(&g_cum[nb]);
    }
    int nseg = 0, kpos = 0, curST = 0, curCUM = 0;
    long long b8 = (long long)bkt * 8;
    #pragma unroll
    for (int d = 0; d < 7; ++d) {
        int cd = __shfl_sync(FULL, cnt, d);
        int md = __shfl_sync(FULL, cum, d);
        if (lane == 0 && cd > 0) {
            bool ext = (nseg > 0) && (md == curCUM + (kpos - curST));
            if (!ext) {
                curST = kpos; curCUM = md;
                g_segtab[b8 + nseg] = make_int2(kpos, __float_as_int((float)(md - kpos)));
                ++nseg;
            }
            kpos += cd;
        }
    }
    if (lane == 0) {
        for (int j = nseg; j < 7; ++j)
            g_segtab[b8 + j] = make_int2(0x7FFFFFFF, 0);
        g_segtab[b8 + 7] = make_int2(kpos, nseg);
    }
}

// placement + per-atom info record; last block: L, F, bpre
__global__ void k_place(int n, int nch) {
    __shared__ int ws[32];
    int t = threadIdx.x;
    int i = blockIdx.x * 1024 + t;
    bool valid = (i < n);
    int tsum = 0, flat = 0;
    if (valid) {
        int pk = g_vec[i];
        int vx = pk & 0xFF, vy = (pk >> 8) & 0xFF, vz = (pk >> 16) & 0xFF;
        flat = vx * g_scal[0] + vy * g_scal[1] + vz;
        int slot = g_cum[flat] + atomicAdd(&g_fill[flat], 1);
        g_tmp[slot] = i;
        tsum = __ldg(&g_segtab[flat * 8 + 7]).x;
    }
    int incl = blkscan1024(tsum, ws);
    if (valid) g_info[i] = make_int4(flat, tsum, incl - tsum, 0);
    if (t == 1023) g_bsum[blockIdx.x] = incl;

    __syncthreads();
    __shared__ int lastflag;
    if (t == 0) {
        __threadfence();
        lastflag = (atomicAdd(&g_done2, 1) == nch - 1);
    }
    __syncthreads();
    if (!lastflag) return;

    if (t < 32) {
        const unsigned FULL = 0xffffffffu;
        int ex[4];
        int s = 0;
        #pragma unroll
        for (int j = 0; j < 4; ++j) {
            int idx = t * 4 + j;
            int x = (idx < nch) ? __ldcg(&g_bsum[idx]) : 0;
            ex[j] = s; s += x;
        }
        int iw = s;
        #pragma unroll
        for (int o = 1; o < 32; o <<= 1) {
            int x = __shfl_up_sync(FULL, iw, o);
            if (t >= o) iw += x;
        }
        int base = iw - s;
        #pragma unroll
        for (int j = 0; j < 4; ++j) {
            int idx = t * 4 + j;
            if (idx < nch) g_bpre[idx] = base + ex[j];
        }
        if (t == 31) { g_L = iw; g_F = 2 * g_P + iw; }
    }
}

// Fused output writer + state cleanup. Bucket warps first (slowest blocks in wave 0).
__global__ void k_emit(float* __restrict__ out,
                       const float* __restrict__ coord,
                       const float* __restrict__ cell,
                       int n, int bktb, int fillb) {
    const unsigned FULL = 0xffffffffu;
    int blk = blockIdx.x;
    int t = threadIdx.x;
    if (blk < bktb) {
        // ---- warp per bucket: stable order restore + pairs + cleanup ----
        __shared__ int s_atom[32][ATCAP];
        int wib = t >> 5, lane = t & 31;
        int bkt = blk * 32 + wib;
        if (bkt >= g_B) return;
        if (blk == 0 && t == 0) { g_done1 = 0; g_done2 = 0; }
        int c = g_counts[bkt];
        if (lane == 0) { g_counts[bkt] = 0; g_fill[bkt] = 0; }
        if (c == 0) return;
        int cum = g_cum[bkt];
        long long F = g_F;
        long long imb = F + 3LL * n;
        long long atb = F + 4LL * n;
        int cl = (c < ATCAP) ? c : ATCAP;
        for (int j = lane; j < cl; j += 32)
            s_atom[wib][j] = g_tmp[cum + j];
        __syncwarp();
        for (int j = lane; j < c; j += 32) {
            int vj = (j < ATCAP) ? s_atom[wib][j] : __ldg(&g_tmp[cum + j]);
            int rank = 0;
            for (int k = 0; k < c; ++k) {
                int vk = (k < ATCAP) ? s_atom[wib][k] : __ldg(&g_tmp[cum + k]);
                rank += (vk < vj);
            }
            int slot = cum + rank;
            out[imb + slot] = (float)vj;
            out[atb + vj]   = (float)slot;
        }
        if (c < 2) return;
        int npr = c * (c - 1) / 2;
        int off = g_poff[bkt];
        int P = g_P;
        float cumf = (float)cum;
        int k = lane;
        if (k < npr) {
            int pl = (int)((1.0f + sqrtf(8.0f * (float)k + 1.0f)) * 0.5f);
            while (pl * (pl - 1) / 2 > k) --pl;
            while ((pl + 1) * pl / 2 <= k) ++pl;
            for (; k < npr; k += 32) {
                while ((pl + 1) * pl / 2 <= k) ++pl;   // monotone carry
                int pu = k - pl * (pl - 1) / 2;
                out[off + k]     = cumf + (float)pu;
                out[P + off + k] = cumf + (float)pl;
            }
        }
    } else if (blk < bktb + fillb) {
        // ---- lower_between: warp per atom, compute-direct, merged segments ----
        int wib = t >> 5, lane = t & 31;
        int w = (blk - bktb) * 32 + wib;
        if (w >= n) return;
        int flat = 0, base = 0;
        if (lane == 0) {
            int4 inf = __ldg(&g_info[w]);
            flat = inf.x;
            base = 2 * g_P + inf.z + __ldg(&g_bpre[w >> 10]);
        }
        flat = __shfl_sync(FULL, flat, 0);
        base = __shfl_sync(FULL, base, 0);
        int2 e = make_int2(0x7FFFFFFF, 0);
        if (lane < 8) e = __ldg(&g_segtab[flat * 8 + lane]);
        int   sK = e.x;
        float fK = __int_as_float(e.y);
        int T    = __shfl_sync(FULL, sK, 7);
        int nseg = __shfl_sync(FULL, __float_as_int(fK), 7);
        float f0 = __shfl_sync(FULL, fK, 0);
        int   s1 = __shfl_sync(FULL, sK, 1); float f1 = __shfl_sync(FULL, fK, 1);
        int   s2 = __shfl_sync(FULL, sK, 2); float f2 = __shfl_sync(FULL, fK, 2);
        int   s3 = __shfl_sync(FULL, sK, 3); float f3 = __shfl_sync(FULL, fK, 3);
        float* p = out + base + lane;
        float kf = (float)lane;
        if (nseg <= 4) {
            for (int k = lane; k < T; k += 32, kf += 32.0f, p += 32) {
                float s = f0;
                if (k >= s1) s = f1;
                if (k >= s2) s = f2;
                if (k >= s3) s = f3;
                *p = s + kf;
            }
        } else {
            int   s4 = __shfl_sync(FULL, sK, 4); float f4 = __shfl_sync(FULL, fK, 4);
            int   s5 = __shfl_sync(FULL, sK, 5); float f5 = __shfl_sync(FULL, fK, 5);
            int   s6 = __shfl_sync(FULL, sK, 6); float f6 = __shfl_sync(FULL, fK, 6);
            for (int k = lane; k < T; k += 32, kf += 32.0f, p += 32) {
                float s = f0;
                if (k >= s1) s = f1;
                if (k >= s2) s = f2;
                if (k >= s3) s = f3;
                if (k >= s4) s = f4;
                if (k >= s5) s = f5;
                if (k >= s6) s = f6;
                *p = s + kf;
            }
        }
    } else {
        // ---- frac ----
        int i = (blk - bktb - fillb) * 1024 + t;
        if (i >= n) return;
        long long F = g_F;
        float d0 = __ldg(cell + 0), d1 = __ldg(cell + 4), d2 = __ldg(cell + 8);
        out[F + 3LL * i + 0] = __ldg(coord + 3 * i + 0) / d0;
        out[F + 3LL * i + 1] = __ldg(coord + 3 * i + 1) / d1;
        out[F + 3LL * i + 2] = __ldg(coord + 3 * i + 2) / d2;
    }
}

extern "C" void kernel_launch(void* const* d_in, const int* in_sizes, int n_in,
                              void* d_out, int out_size) {
    const float* coord = (const float*)d_in[0];
    const float* cell  = (const float*)d_in[1];
    float* out = (float*)d_out;
    int n = in_sizes[0] / 3;
    int nblk = (n + 1023) / 1024;       // 98

    k_bucket<<<nblk, 1024>>>(coord, cell, n);
    k_seg<<<MAXB / 32, 1024>>>();
    k_place<<<nblk, 1024>>>(n, nblk);

    int bktb  = MAXB / 32;              // 256 blocks, warp per bucket (scheduled first)
    int fillb = (n + 31) / 32;          // 3125 blocks, warp per atom
    int tailb = nblk;                   // 98 blocks, frac
    k_emit<<<bktb + fillb + tailb, 1024>>>(out, coord, cell, n, bktb, fillb);
}

// round 17
// speedup vs baseline: 1.2655x; 1.1405x over previous
#include <cuda_runtime.h>

// CellListComputer: cell-list build, 100k atoms, 20^3 buckets, sm_103a.
// Output layout (float32): [pairs_u | pairs_l | lower_between | frac | imidx | atidx]
// 4 launches:
//   k_bucket : bucketize + per-bucket atomic counts; last block: u64 scan -> cum,poff,P
//   k_seg    : warp/bucket: MERGED segment table (typ. <=4 segs) -> g_segtab
//   k_place  : placement via atomicAdd; info {flat,T,aoffL}; scan -> L,F,bpre
//   k_emit   : [bucket warps FIRST: sort + pairs + cleanup]
//              [fill: warp = 4 x 8-lane groups, one atom each, compute-direct] [frac]
// State invariant: g_counts/g_fill/g_done* zero on entry (static zero-init first
// call; k_emit bucket warps restore zeros every call; fill reads only g_segtab).

#define MAXN   100000
#define MAXB   8192
#define MAXCH  104
#define ATCAP  64

__device__ int g_grid[3];
__device__ int g_scal[3];
__device__ int g_B;
__device__ int g_P;
__device__ int g_L;
__device__ int g_F;          // 2*P + L (start of frac section)
__device__ unsigned g_done1, g_done2;

__device__ __align__(16) int g_counts[MAXB];
__device__ __align__(16) int g_fill[MAXB];
__device__ __align__(16) int g_cum[MAXB];
__device__ __align__(16) int g_poff[MAXB];
// [bkt][j<7] = {start_k, f32(cum-start)}; unused -> {INT_MAX,0}; [bkt][7] = {T, nseg}
__device__ __align__(16) int2 g_segtab[MAXB * 8];
__device__ int g_vec[MAXN];                  // packed vx | vy<<8 | vz<<16
__device__ int g_tmp[MAXN];                  // unordered bucket-sliced atom indices
__device__ __align__(16) int4 g_info[MAXN];  // per-atom {flat, T, aoffL, 0}
__device__ int g_bsum[MAXCH];
__device__ int g_bpre[MAXCH];

// inclusive block scan (int), blockDim.x == 1024
__device__ __forceinline__ int blkscan1024(int v, int* wsum) {
    int t = threadIdx.x, lane = t & 31, w = t >> 5;
    #pragma unroll
    for (int o = 1; o < 32; o <<= 1) {
        int x = __shfl_up_sync(0xffffffffu, v, o);
        if (lane >= o) v += x;
    }
    if (lane == 31) wsum[w] = v;
    __syncthreads();
    if (w == 0) {
        int s = wsum[lane];
        #pragma unroll
        for (int o = 1; o < 32; o <<= 1) {
            int x = __shfl_up_sync(0xffffffffu, s, o);
            if (lane >= o) s += x;
        }
        wsum[lane] = s;
    }
    __syncthreads();
    return v + ((w > 0) ? wsum[w - 1] : 0);
}

// inclusive block scan (u64 packed), blockDim.x == 1024
__device__ __forceinline__ unsigned long long
blkscan1024_u64(unsigned long long v, unsigned long long* wsum) {
    int t = threadIdx.x, lane = t & 31, w = t >> 5;
    #pragma unroll
    for (int o = 1; o < 32; o <<= 1) {
        unsigned long long x = __shfl_up_sync(0xffffffffu, v, o);
        if (lane >= o) v += x;
    }
    if (lane == 31) wsum[w] = v;
    __syncthreads();
    if (w == 0) {
        unsigned long long s = wsum[lane];
        #pragma unroll
        for (int o = 1; o < 32; o <<= 1) {
            unsigned long long x = __shfl_up_sync(0xffffffffu, s, o);
            if (lane >= o) s += x;
        }
        wsum[lane] = s;
    }
    __syncthreads();
    return v + ((w > 0) ? wsum[w - 1] : 0ull);
}

// bucketize + count; last-arriving block scans buckets -> g_cum, g_poff, g_P
__global__ void k_bucket(const float* __restrict__ coord,
                         const float* __restrict__ cell, int n) {
    int i = blockIdx.x * 1024 + threadIdx.x;
    float d0 = __ldg(cell + 0), d1 = __ldg(cell + 4), d2 = __ldg(cell + 8);
    float bl = (float)(5.2 / 1.0 + 1e-5);
    int g0 = (int)floorf(d0 / bl) + 1;
    int g1 = (int)floorf(d1 / bl) + 1;
    int g2 = (int)floorf(d2 / bl) + 1;
    if (blockIdx.x == 0 && threadIdx.x == 0) {
        g_grid[0] = g0; g_grid[1] = g1; g_grid[2] = g2;
        g_B = g0 * g1 * g2;
        g_scal[0] = g1 * g2; g_scal[1] = g1; g_scal[2] = 1;
    }
    if (i < n) {
        float fx = __ldg(coord + 3 * i + 0) / d0;
        float fy = __ldg(coord + 3 * i + 1) / d1;
        float fz = __ldg(coord + 3 * i + 2) / d2;
        int vx = __float2int_rn(fx * (float)(g0 - 1));
        int vy = __float2int_rn(fy * (float)(g1 - 1));
        int vz = __float2int_rn(fz * (float)(g2 - 1));
        int flat = vx * (g1 * g2) + vy * g1 + vz;   // scal = [g1*g2, g1, 1]
        g_vec[i] = vx | (vy << 8) | (vz << 16);
        atomicAdd(&g_counts[flat], 1);
    }
    __syncthreads();
    __shared__ int lastflag;
    if (threadIdx.x == 0) {
        __threadfence();
        lastflag = (atomicAdd(&g_done1, 1) == gridDim.x - 1);
    }
    __syncthreads();
    if (!lastflag) return;

    // ---- bucket scan: counts + pair-counts packed in u64, 8 buckets/thread ----
    __shared__ unsigned long long ws64[32];
    int t = threadIdx.x;
    int cc[8], eC[8], eP[8];
    #pragma unroll
    for (int j = 0; j < 8; ++j) cc[j] = __ldcg(&g_counts[t * 8 + j]);
    int sC = 0, sP = 0;
    #pragma unroll
    for (int j = 0; j < 8; ++j) {
        eC[j] = sC; sC += cc[j];
        eP[j] = sP; sP += cc[j] * (cc[j] - 1) / 2;
    }
    unsigned long long v = ((unsigned long long)(unsigned)sC << 32) | (unsigned)sP;
    unsigned long long incl = blkscan1024_u64(v, ws64);
    unsigned long long excl = incl - v;
    int baseC = (int)(excl >> 32);
    int baseP = (int)(excl & 0xffffffffull);
    int4 oc0 = make_int4(baseC + eC[0], baseC + eC[1], baseC + eC[2], baseC + eC[3]);
    int4 oc1 = make_int4(baseC + eC[4], baseC + eC[5], baseC + eC[6], baseC + eC[7]);
    int4 op0 = make_int4(baseP + eP[0], baseP + eP[1], baseP + eP[2], baseP + eP[3]);
    int4 op1 = make_int4(baseP + eP[4], baseP + eP[5], baseP + eP[6], baseP + eP[7]);
    *reinterpret_cast<int4*>(&g_cum[t * 8])      = oc0;
    *reinterpret_cast<int4*>(&g_cum[t * 8 + 4])  = oc1;
    *reinterpret_cast<int4*>(&g_poff[t * 8])     = op0;
    *reinterpret_cast<int4*>(&g_poff[t * 8 + 4]) = op1;
    if (t == 1023) g_P = (int)(incl & 0xffffffffull);
}

// warp per bucket: merged segment table -> g_segtab
__global__ void k_seg() {
    const unsigned FULL = 0xffffffffu;
    int t = threadIdx.x, wib = t >> 5, lane = t & 31;
    int bkt = blockIdx.x * 32 + wib;
    if (bkt >= g_B) return;

    int cnt = 0, cum = 0;
    if (lane < 7) {
        int s0 = g_scal[0], s1g = g_scal[1];
        int g0 = g_grid[0], g1 = g_grid[1], g2 = g_grid[2];
        int vx = bkt / s0; int r = bkt - vx * s0;
        int vy = r / s1g;  int vz = r - vy * s1g;
        int dx = (lane >> 2) - 1;
        int dy = ((lane >> 1) & 1) - 1;
        int dz = (lane & 1) - 1;
        int nx = vx + dx; if (nx < 0) nx += g0;
        int ny = vy + dy; if (ny < 0) ny += g1;
        int nz = vz + dz; if (nz < 0) nz += g2;
        int nb = nx * s0 + ny * s1g + nz;
        cnt = __ldg(&g_counts[nb]);
        cum = __ldg(&g_cum[nb]);
    }
    int nseg = 0, kpos = 0, curST = 0, curCUM = 0;
    long long b8 = (long long)bkt * 8;
    #pragma unroll
    for (int d = 0; d < 7; ++d) {
        int cd = __shfl_sync(FULL, cnt, d);
        int md = __shfl_sync(FULL, cum, d);
        if (lane == 0 && cd > 0) {
            bool ext = (nseg > 0) && (md == curCUM + (kpos - curST));
            if (!ext) {
                curST = kpos; curCUM = md;
                g_segtab[b8 + nseg] = make_int2(kpos, __float_as_int((float)(md - kpos)));
                ++nseg;
            }
            kpos += cd;
        }
    }
    if (lane == 0) {
        for (int j = nseg; j < 7; ++j)
            g_segtab[b8 + j] = make_int2(0x7FFFFFFF, 0);
        g_segtab[b8 + 7] = make_int2(kpos, nseg);
    }
}

// placement + per-atom info record; last block: L, F, bpre
__global__ void k_place(int n, int nch) {
    __shared__ int ws[32];
    int t = threadIdx.x;
    int i = blockIdx.x * 1024 + t;
    bool valid = (i < n);
    int tsum = 0, flat = 0;
    if (valid) {
        int pk = g_vec[i];
        int vx = pk & 0xFF, vy = (pk >> 8) & 0xFF, vz = (pk >> 16) & 0xFF;
        flat = vx * g_scal[0] + vy * g_scal[1] + vz;
        int slot = g_cum[flat] + atomicAdd(&g_fill[flat], 1);
        g_tmp[slot] = i;
        tsum = __ldg(&g_segtab[flat * 8 + 7]).x;
    }
    int incl = blkscan1024(tsum, ws);
    if (valid) g_info[i] = make_int4(flat, tsum, incl - tsum, 0);
    if (t == 1023) g_bsum[blockIdx.x] = incl;

    __syncthreads();
    __shared__ int lastflag;
    if (t == 0) {
        __threadfence();
        lastflag = (atomicAdd(&g_done2, 1) == nch - 1);
    }
    __syncthreads();
    if (!lastflag) return;

    if (t < 32) {
        const unsigned FULL = 0xffffffffu;
        int ex[4];
        int s = 0;
        #pragma unroll
        for (int j = 0; j < 4; ++j) {
            int idx = t * 4 + j;
            int x = (idx < nch) ? __ldcg(&g_bsum[idx]) : 0;
            ex[j] = s; s += x;
        }
        int iw = s;
        #pragma unroll
        for (int o = 1; o < 32; o <<= 1) {
            int x = __shfl_up_sync(FULL, iw, o);
            if (t >= o) iw += x;
        }
        int base = iw - s;
        #pragma unroll
        for (int j = 0; j < 4; ++j) {
            int idx = t * 4 + j;
            if (idx < nch) g_bpre[idx] = base + ex[j];
        }
        if (t == 31) { g_L = iw; g_F = 2 * g_P + iw; }
    }
}

// Fused output writer + state cleanup. Bucket warps first (slowest blocks in wave 0).
__global__ void k_emit(float* __restrict__ out,
                       const float* __restrict__ coord,
                       const float* __restrict__ cell,
                       int n, int bktb, int fillb) {
    const unsigned FULL = 0xffffffffu;
    int blk = blockIdx.x;
    int t = threadIdx.x;
    if (blk < bktb) {
        // ---- warp per bucket: stable order restore + pairs + cleanup ----
        __shared__ int s_atom[32][ATCAP];
        int wib = t >> 5, lane = t & 31;
        int bkt = blk * 32 + wib;
        if (bkt >= g_B) return;
        if (blk == 0 && t == 0) { g_done1 = 0; g_done2 = 0; }
        int c = g_counts[bkt];
        if (lane == 0) { g_counts[bkt] = 0; g_fill[bkt] = 0; }
        if (c == 0) return;
        int cum = g_cum[bkt];
        long long F = g_F;
        long long imb = F + 3LL * n;
        long long atb = F + 4LL * n;
        int cl = (c < ATCAP) ? c : ATCAP;
        for (int j = lane; j < cl; j += 32)
            s_atom[wib][j] = g_tmp[cum + j];
        __syncwarp();
        for (int j = lane; j < c; j += 32) {
            int vj = (j < ATCAP) ? s_atom[wib][j] : __ldg(&g_tmp[cum + j]);
            int rank = 0;
            for (int k = 0; k < c; ++k) {
                int vk = (k < ATCAP) ? s_atom[wib][k] : __ldg(&g_tmp[cum + k]);
                rank += (vk < vj);
            }
            int slot = cum + rank;
            out[imb + slot] = (float)vj;
            out[atb + vj]   = (float)slot;
        }
        if (c < 2) return;
        int npr = c * (c - 1) / 2;
        int off = g_poff[bkt];
        int P = g_P;
        float cumf = (float)cum;
        int k = lane;
        if (k < npr) {
            int pl = (int)((1.0f + sqrtf(8.0f * (float)k + 1.0f)) * 0.5f);
            while (pl * (pl - 1) / 2 > k) --pl;
            while ((pl + 1) * pl / 2 <= k) ++pl;
            for (; k < npr; k += 32) {
                while ((pl + 1) * pl / 2 <= k) ++pl;   // monotone carry
                int pu = k - pl * (pl - 1) / 2;
                out[off + k]     = cumf + (float)pu;
                out[P + off + k] = cumf + (float)pl;
            }
        }
    } else if (blk < bktb + fillb) {
        // ---- lower_between: warp = 4 x 8-lane groups, one atom each ----
        int wib = t >> 5, lane = t & 31;
        int wbase = ((blk - bktb) * 32 + wib) * 4;
        if (wbase >= n) return;
        int4 inf = make_int4(0, 0, 0, 0);
        int baseL = 0;
        if (lane < 4 && wbase + lane < n) {
            inf = __ldg(&g_info[wbase + lane]);
            baseL = 2 * g_P + inf.z + __ldg(&g_bpre[(wbase + lane) >> 10]);
        }
        int grp = lane >> 3, sub = lane & 7;
        int flat = __shfl_sync(FULL, inf.x, grp);
        int base = __shfl_sync(FULL, baseL, grp);
        bool gvalid = (wbase + grp) < n;
        int2 e = __ldg(&g_segtab[flat * 8 + sub]);
        int T    = gvalid ? __shfl_sync(FULL, e.x, 7, 8) : 0;
        int nseg = __shfl_sync(FULL, e.y, 7, 8);
        float f0 = __shfl_sync(FULL, __int_as_float(e.y), 0, 8);
        int   s1 = __shfl_sync(FULL, e.x, 1, 8); float f1 = __shfl_sync(FULL, __int_as_float(e.y), 1, 8);
        int   s2 = __shfl_sync(FULL, e.x, 2, 8); float f2 = __shfl_sync(FULL, __int_as_float(e.y), 2, 8);
        int   s3 = __shfl_sync(FULL, e.x, 3, 8); float f3 = __shfl_sync(FULL, __int_as_float(e.y), 3, 8);
        float* p = out + base + sub;
        float kf = (float)sub;
        if (__all_sync(FULL, nseg <= 4 || !gvalid)) {
            for (int k = sub; k < T; k += 8, kf += 8.0f, p += 8) {
                float s = f0;
                if (k >= s1) s = f1;
                if (k >= s2) s = f2;
                if (k >= s3) s = f3;
                *p = s + kf;
            }
        } else {
            int   s4 = __shfl_sync(FULL, e.x, 4, 8); float f4 = __shfl_sync(FULL, __int_as_float(e.y), 4, 8);
            int   s5 = __shfl_sync(FULL, e.x, 5, 8); float f5 = __shfl_sync(FULL, __int_as_float(e.y), 5, 8);
            int   s6 = __shfl_sync(FULL, e.x, 6, 8); float f6 = __shfl_sync(FULL, __int_as_float(e.y), 6, 8);
            for (int k = sub; k < T; k += 8, kf += 8.0f, p += 8) {
                float s = f0;
                if (k >= s1) s = f1;
                if (k >= s2) s = f2;
                if (k >= s3) s = f3;
                if (k >= s4) s = f4;
                if (k >= s5) s = f5;
                if (k >= s6) s = f6;
                *p = s + kf;
            }
        }
    } else {
        // ---- frac ----
        int i = (blk - bktb - fillb) * 1024 + t;
        if (i >= n) return;
        long long F = g_F;
        float d0 = __ldg(cell + 0), d1 = __ldg(cell + 4), d2 = __ldg(cell + 8);
        out[F + 3LL * i + 0] = __ldg(coord + 3 * i + 0) / d0;
        out[F + 3LL * i + 1] = __ldg(coord + 3 * i + 1) / d1;
        out[F + 3LL * i + 2] = __ldg(coord + 3 * i + 2) / d2;
    }
}

extern "C" void kernel_launch(void* const* d_in, const int* in_sizes, int n_in,
                              void* d_out, int out_size) {
    const float* coord = (const float*)d_in[0];
    const float* cell  = (const float*)d_in[1];
    float* out = (float*)d_out;
    int n = in_sizes[0] / 3;
    int nblk = (n + 1023) / 1024;       // 98

    k_bucket<<<nblk, 1024>>>(coord, cell, n);
    k_seg<<<MAXB / 32, 1024>>>();
    k_place<<<nblk, 1024>>>(n, nblk);

    int bktb  = MAXB / 32;              // 256 blocks, warp per bucket (scheduled first)
    int fillb = (n + 127) / 128;        // 782 blocks: warp = 4 atoms (8 lanes each)
    int tailb = nblk;                   // 98 blocks, frac
    k_emit<<<bktb + fillb + tailb, 1024>>>(out, coord, cell, n, bktb, fillb);
}